// round 14
// baseline (speedup 1.0000x reference)
#include <cuda_runtime.h>
#include <cuda_bf16.h>
#include <math.h>

#define NSEQ 250000
#define DIM 32
#define NBAGS 100
#define TSEQ 16                 /* 2 seqs per warp: w and w+8 */
#define NBLK (NSEQ / TSEQ)      /* 15625 */
#define XROW 20                 /* natural x row (40B); dual-copy fixes align */
#define H1ROW 40                /* padded h1 row (80B, 16B-aligned stride) */

/* dynamic smem (bytes) */
#define XS0_OFF 0                        /* copy0: 640*40 = 25600 */
#define XS1_OFF 25624                    /* copy1 base ≡ 8 (mod 16) */
#define H1_OFF  51232                    /* 592*80 = 47360 */
#define ES_OFF  (51232 + 47360)          /* 98592 */
#define SM_TOTAL (ES_OFF + TSEQ * DIM * 4)   /* 100640 */

__device__ float g_embed[NSEQ * DIM];
__device__ float g_scores[NSEQ];
__device__ uint4 d_frag1[5][2][32];
__device__ uint4 d_frag2[8][2][32];

__device__ __forceinline__ float selu_f(float x) {
    const float s = 1.0507009873554805f;
    const float sa = 1.0507009873554805f * 1.6732632423543772f;
    float p = fmaxf(x, 0.f), m = fminf(x, 0.f);
    return fmaf(s, p, sa * (__expf(m) - 1.f));
}
__device__ __forceinline__ unsigned pk(float lo, float hi) {
    __nv_bfloat162 t = __floats2bfloat162_rn(lo, hi);
    return *reinterpret_cast<unsigned*>(&t);
}
__device__ __forceinline__ void mma16(float* c, unsigned a0, unsigned a1,
                                      unsigned a2, unsigned a3,
                                      unsigned b0, unsigned b1) {
    asm volatile(
        "mma.sync.aligned.m16n8k16.row.col.f32.bf16.bf16.f32 "
        "{%0,%1,%2,%3}, {%4,%5,%6,%7}, {%8,%9}, {%0,%1,%2,%3};\n"
        : "+f"(c[0]), "+f"(c[1]), "+f"(c[2]), "+f"(c[3])
        : "r"(a0), "r"(a1), "r"(a2), "r"(a3), "r"(b0), "r"(b1));
}
__device__ __forceinline__ void ldsm4(unsigned& r0, unsigned& r1,
                                      unsigned& r2, unsigned& r3, unsigned a) {
    asm volatile("ldmatrix.sync.aligned.m8n8.x4.shared.b16 {%0,%1,%2,%3}, [%4];"
                 : "=r"(r0), "=r"(r1), "=r"(r2), "=r"(r3) : "r"(a));
}

__global__ void nop_kernel() {}

__global__ void pack_kernel(const float* __restrict__ w1,
                            const float* __restrict__ w2)
{
    const int lane = threadIdx.x & 31;
    if (threadIdx.x >= 32) return;
    const int lr = lane >> 2, lc = lane & 3;
    for (int ks = 0; ks < 5; ++ks)          /* conv1: K=80 exact */
        for (int ntp = 0; ntp < 2; ++ntp) {
            const int k0 = 16 * ks + 2 * lc;
            const int n0 = 16 * ntp + lr, n1 = n0 + 8;
            uint4 v;
            v.x = pk(w1[k0 * 32 + n0],       w1[(k0 + 1) * 32 + n0]);
            v.y = pk(w1[(k0 + 8) * 32 + n0], w1[(k0 + 9) * 32 + n0]);
            v.z = pk(w1[k0 * 32 + n1],       w1[(k0 + 1) * 32 + n1]);
            v.w = pk(w1[(k0 + 8) * 32 + n1], w1[(k0 + 9) * 32 + n1]);
            d_frag1[ks][ntp][lane] = v;
        }
    for (int ks = 0; ks < 8; ++ks)          /* conv2: K=128 */
        for (int ntp = 0; ntp < 2; ++ntp) {
            const int k0 = 16 * ks + 2 * lc;
            const int n0 = 16 * ntp + lr, n1 = n0 + 8;
            uint4 v;
            v.x = pk(w2[k0 * 32 + n0],       w2[(k0 + 1) * 32 + n0]);
            v.y = pk(w2[(k0 + 8) * 32 + n0], w2[(k0 + 9) * 32 + n0]);
            v.z = pk(w2[k0 * 32 + n1],       w2[(k0 + 1) * 32 + n1]);
            v.w = pk(w2[(k0 + 8) * 32 + n1], w2[(k0 + 9) * 32 + n1]);
            d_frag2[ks][ntp][lane] = v;
        }
}

// ---------------------------------------------------------------------------
// seq_kernel: warp owns seqs (w, w+8); conv1 K=80 via dual-copy parity
// ---------------------------------------------------------------------------
__global__ __launch_bounds__(256, 2) void seq_kernel(
    const float* __restrict__ x,
    const float* __restrict__ b1, const float* __restrict__ b2,
    const float* __restrict__ aw1, const float* __restrict__ ab1,
    const float* __restrict__ aw2, const float* __restrict__ ab2,
    const float* __restrict__ aw3, const float* __restrict__ ab3)
{
    extern __shared__ char sm[];
    __nv_bfloat16* h1s = (__nv_bfloat16*)(sm + H1_OFF);
    float (*es_s)[DIM] = (float(*)[DIM])(sm + ES_OFF);

    const int tid = threadIdx.x;
    const int warp = tid >> 5, lane = tid & 31;
    const int lr = lane >> 2, lc = lane & 3;
    const int rowq = lane & 15;
    const int khalf = (lane >> 4) * 8;
    const unsigned sb = (unsigned)__cvta_generic_to_shared(sm);
    const unsigned h1_s = sb + H1_OFF;

    // ---- stage x: flat bf16 conversion into BOTH copies ----
    {
        const float4* xg = (const float4*)(x + (long)blockIdx.x * (TSEQ * 40 * 20));
        uint2* x0 = (uint2*)(sm + XS0_OFF);
        uint2* x1 = (uint2*)(sm + XS1_OFF);
        #pragma unroll
        for (int i = tid; i < TSEQ * 40 * 20 / 4; i += 256) {
            const float4 v = xg[i];
            const uint2 p = make_uint2(pk(v.x, v.y), pk(v.z, v.w));
            x0[i] = p;
            x1[i] = p;
        }
    }

    // ---- conv1 fragments + bias ----
    unsigned B1r[5][4][2];
    #pragma unroll
    for (int ks = 0; ks < 5; ++ks) {
        const uint4 v0 = d_frag1[ks][0][lane];
        const uint4 v1 = d_frag1[ks][1][lane];
        B1r[ks][0][0] = v0.x; B1r[ks][0][1] = v0.y;
        B1r[ks][1][0] = v0.z; B1r[ks][1][1] = v0.w;
        B1r[ks][2][0] = v1.x; B1r[ks][2][1] = v1.y;
        B1r[ks][3][0] = v1.z; B1r[ks][3][1] = v1.w;
    }
    float bias1[4][2];
    #pragma unroll
    for (int nt = 0; nt < 4; ++nt) {
        bias1[nt][0] = __ldg(&b1[nt * 8 + 2 * lc]);
        bias1[nt][1] = __ldg(&b1[nt * 8 + 2 * lc + 1]);
    }
    __syncthreads();

    // per-warp sequence bases (natural layout)
    const int xbA = warp * 40,       xbB = (warp + 8) * 40;   // x rows
    const int hbA = warp * 37,       hbB = (warp + 8) * 37;   // h1 rows

    // ---- conv1: 5 tiles over 74 logical rows (A: 0..36, B: 37..73) ----
    #pragma unroll
    for (int tile = 0; tile < 5; ++tile) {
        int rc = tile * 16 + rowq;
        if (rc > 73) rc = 73;
        const int fr = (rc < 37) ? xbA + rc : xbB + (rc - 37);
        // copy by row parity keeps every lane address 16B-aligned
        const unsigned abase = sb + ((fr & 1) ? XS1_OFF : XS0_OFF)
                             + (unsigned)fr * (XROW * 2) + khalf * 2;
        float acc[4][4];
        #pragma unroll
        for (int nt = 0; nt < 4; ++nt) {
            acc[nt][0] = bias1[nt][0]; acc[nt][1] = bias1[nt][1];
            acc[nt][2] = bias1[nt][0]; acc[nt][3] = bias1[nt][1];
        }
        #pragma unroll
        for (int ks = 0; ks < 5; ++ks) {
            unsigned a0, a1, a2, a3;
            ldsm4(a0, a1, a2, a3, abase + ks * 32);
            #pragma unroll
            for (int nt = 0; nt < 4; ++nt)
                mma16(acc[nt], a0, a1, a2, a3, B1r[ks][nt][0], B1r[ks][nt][1]);
        }
        const int r0 = tile * 16 + lr;              // <= 71, valid
        int r1 = r0 + 8; if (r1 > 73) r1 = 73;      // dup stores benign
        const int g0 = (r0 < 37) ? hbA + r0 : hbB + (r0 - 37);
        const int g1 = (r1 < 37) ? hbA + r1 : hbB + (r1 - 37);
        #pragma unroll
        for (int nt = 0; nt < 4; ++nt) {
            const int col = nt * 8 + 2 * lc;
            *(unsigned*)(h1s + g0 * H1ROW + col) =
                pk(selu_f(acc[nt][0]), selu_f(acc[nt][1]));
            *(unsigned*)(h1s + g1 * H1ROW + col) =
                pk(selu_f(acc[nt][2]), selu_f(acc[nt][3]));
        }
    }

    // ---- conv2 fragments + bias ----
    unsigned B2r[8][4][2];
    #pragma unroll
    for (int ks = 0; ks < 8; ++ks) {
        const uint4 v0 = d_frag2[ks][0][lane];
        const uint4 v1 = d_frag2[ks][1][lane];
        B2r[ks][0][0] = v0.x; B2r[ks][0][1] = v0.y;
        B2r[ks][1][0] = v0.z; B2r[ks][1][1] = v0.w;
        B2r[ks][2][0] = v1.x; B2r[ks][2][1] = v1.y;
        B2r[ks][3][0] = v1.z; B2r[ks][3][1] = v1.w;
    }
    float bias2[4][2];
    #pragma unroll
    for (int nt = 0; nt < 4; ++nt) {
        bias2[nt][0] = __ldg(&b2[nt * 8 + 2 * lc]);
        bias2[nt][1] = __ldg(&b2[nt * 8 + 2 * lc + 1]);
    }
    __syncwarp();   // h1 for this warp's seqs written only by this warp

    // ---- conv2: 5 tiles over 68 logical rows (A: 0..33, B: 34..67) ----
    float vmA[4][2], vmB[4][2];
    #pragma unroll
    for (int nt = 0; nt < 4; ++nt) {
        vmA[nt][0] = -INFINITY; vmA[nt][1] = -INFINITY;
        vmB[nt][0] = -INFINITY; vmB[nt][1] = -INFINITY;
    }

    #pragma unroll
    for (int tile = 0; tile < 5; ++tile) {
        int rc = tile * 16 + rowq;
        if (rc > 67) rc = 67;
        const int fr = (rc < 34) ? hbA + rc : hbB + (rc - 34);
        const unsigned abase = h1_s + (fr * H1ROW + khalf) * 2;
        float acc[4][4];
        #pragma unroll
        for (int nt = 0; nt < 4; ++nt) {
            acc[nt][0] = bias2[nt][0]; acc[nt][1] = bias2[nt][1];
            acc[nt][2] = bias2[nt][0]; acc[nt][3] = bias2[nt][1];
        }
        #pragma unroll
        for (int ks = 0; ks < 8; ++ks) {
            unsigned a0, a1, a2, a3;
            ldsm4(a0, a1, a2, a3,
                  abase + ((ks >> 1) * H1ROW + (ks & 1) * 16) * 2);
            #pragma unroll
            for (int nt = 0; nt < 4; ++nt)
                mma16(acc[nt], a0, a1, a2, a3, B2r[ks][nt][0], B2r[ks][nt][1]);
        }
        #pragma unroll
        for (int nt = 0; nt < 4; ++nt) {
            if (tile < 2) {                                    // rows 0..31: A
                vmA[nt][0] = fmaxf(vmA[nt][0], fmaxf(acc[nt][0], acc[nt][2]));
                vmA[nt][1] = fmaxf(vmA[nt][1], fmaxf(acc[nt][1], acc[nt][3]));
            } else if (tile == 2) {                            // 32+lr / 40+lr
                if (lr < 2) {                                  // rows 32,33: A
                    vmA[nt][0] = fmaxf(vmA[nt][0], acc[nt][0]);
                    vmA[nt][1] = fmaxf(vmA[nt][1], acc[nt][1]);
                } else {                                       // rows 34..39: B
                    vmB[nt][0] = fmaxf(vmB[nt][0], acc[nt][0]);
                    vmB[nt][1] = fmaxf(vmB[nt][1], acc[nt][1]);
                }
                vmB[nt][0] = fmaxf(vmB[nt][0], acc[nt][2]);    // rows 40..47: B
                vmB[nt][1] = fmaxf(vmB[nt][1], acc[nt][3]);
            } else {                                           // rows 48..67+: B
                vmB[nt][0] = fmaxf(vmB[nt][0], fmaxf(acc[nt][0], acc[nt][2]));
                vmB[nt][1] = fmaxf(vmB[nt][1], fmaxf(acc[nt][1], acc[nt][3]));
            }
        }
        if (tile == 2) {   // seq A complete: reduce + store, free vmA
            #pragma unroll
            for (int nt = 0; nt < 4; ++nt)
                #pragma unroll
                for (int j = 0; j < 2; ++j) {
                    float v = vmA[nt][j];
                    v = fmaxf(v, __shfl_xor_sync(0xffffffffu, v, 4));
                    v = fmaxf(v, __shfl_xor_sync(0xffffffffu, v, 8));
                    v = fmaxf(v, __shfl_xor_sync(0xffffffffu, v, 16));
                    vmA[nt][j] = v;
                }
            if (lane < 4)
                #pragma unroll
                for (int nt = 0; nt < 4; ++nt) {
                    es_s[warp][nt * 8 + 2 * lane]     = selu_f(vmA[nt][0]);
                    es_s[warp][nt * 8 + 2 * lane + 1] = selu_f(vmA[nt][1]);
                }
            __syncwarp();
            g_embed[((long)blockIdx.x * TSEQ + warp) * DIM + lane] = es_s[warp][lane];
        }
    }
    // seq B reduce + store
    #pragma unroll
    for (int nt = 0; nt < 4; ++nt)
        #pragma unroll
        for (int j = 0; j < 2; ++j) {
            float v = vmB[nt][j];
            v = fmaxf(v, __shfl_xor_sync(0xffffffffu, v, 4));
            v = fmaxf(v, __shfl_xor_sync(0xffffffffu, v, 8));
            v = fmaxf(v, __shfl_xor_sync(0xffffffffu, v, 16));
            vmB[nt][j] = v;
        }
    if (lane < 4)
        #pragma unroll
        for (int nt = 0; nt < 4; ++nt) {
            es_s[warp + 8][nt * 8 + 2 * lane]     = selu_f(vmB[nt][0]);
            es_s[warp + 8][nt * 8 + 2 * lane + 1] = selu_f(vmB[nt][1]);
        }
    __syncwarp();
    g_embed[((long)blockIdx.x * TSEQ + warp + 8) * DIM + lane] = es_s[warp + 8][lane];

    // ---- attention MLP: warp handles its two seqs ----
    #pragma unroll
    for (int h = 0; h < 2; ++h) {
        const int srow = warp + 8 * h;
        const float* e = es_s[srow];
        const int j = lane;
        float a1v = __ldg(&ab1[j]);
        #pragma unroll 8
        for (int i = 0; i < DIM; ++i)
            a1v = fmaf(e[i], __ldg(&aw1[i * DIM + j]), a1v);
        a1v = selu_f(a1v);
        float a2v = __ldg(&ab2[j]);
        #pragma unroll 8
        for (int i = 0; i < DIM; ++i)
            a2v = fmaf(__shfl_sync(0xffffffffu, a1v, i), __ldg(&aw2[i * DIM + j]), a2v);
        a2v = selu_f(a2v);
        float sc = a2v * __ldg(&aw3[j]);
        #pragma unroll
        for (int o = 16; o > 0; o >>= 1) sc += __shfl_xor_sync(0xffffffffu, sc, o);
        if (j == 0)
            g_scores[(long)blockIdx.x * TSEQ + srow] = sc + __ldg(&ab3[0]);
    }
}

// ---------------------------------------------------------------------------
// bag pipeline (unchanged, validated)
// ---------------------------------------------------------------------------
__global__ __launch_bounds__(1024) void bag_all_kernel(
    const int* __restrict__ nper,
    const float* __restrict__ oaw1, const float* __restrict__ oab1,
    const float* __restrict__ oaw2, const float* __restrict__ oab2,
    const float* __restrict__ obw1, const float* __restrict__ obb1,
    const float* __restrict__ obw2, const float* __restrict__ obb2,
    float* __restrict__ out)
{
    __shared__ float red[1024];
    __shared__ float part[32][33];
    __shared__ float pooled[DIM], hA[DIM], hB[DIM];
    __shared__ int s_off, s_cnt;
    __shared__ float s_mx, s_dn;

    const int tid = threadIdx.x, b = blockIdx.x;
    if (tid == 0) {
        int off = 0;
        for (int i = 0; i < b; ++i) off += nper[i];
        s_off = off; s_cnt = nper[b];
    }
    __syncthreads();
    const int off = s_off, cnt = s_cnt;

    float lm = -INFINITY;
    for (int i = tid; i < cnt; i += 1024) lm = fmaxf(lm, g_scores[off + i]);
    red[tid] = lm; __syncthreads();
    for (int s = 512; s > 0; s >>= 1) {
        if (tid < s) red[tid] = fmaxf(red[tid], red[tid + s]);
        __syncthreads();
    }
    if (tid == 0) s_mx = red[0];
    __syncthreads();
    const float mx = s_mx;

    float ls = 0.f;
    for (int i = tid; i < cnt; i += 1024) ls += __expf(g_scores[off + i] - mx);
    red[tid] = ls; __syncthreads();
    for (int s = 512; s > 0; s >>= 1) {
        if (tid < s) red[tid] += red[tid + s];
        __syncthreads();
    }
    if (tid == 0) s_dn = red[0];
    __syncthreads();
    const float dn = s_dn;

    const int g = tid >> 5, c = tid & 31;
    float acc = 0.f;
    for (int p = g; p < cnt; p += 32) {
        const float wgt = __expf(g_scores[off + p] - mx);
        acc = fmaf(wgt, g_embed[(long)(off + p) * DIM + c], acc);
    }
    part[g][c] = acc;
    __syncthreads();
    if (tid < DIM) {
        float s = 0.f;
        #pragma unroll
        for (int gg = 0; gg < 32; ++gg) s += part[gg][tid];
        pooled[tid] = s / dn;
    }
    __syncthreads();

    if (tid < DIM) {
        float v = __ldg(&oab1[tid]);
        #pragma unroll 8
        for (int i = 0; i < DIM; ++i) v = fmaf(pooled[i], __ldg(&oaw1[i * DIM + tid]), v);
        hA[tid] = selu_f(v);
    } else if (tid < 2 * DIM) {
        const int k = tid - DIM;
        float v = __ldg(&obb1[k]);
        #pragma unroll 8
        for (int i = 0; i < DIM; ++i) v = fmaf(pooled[i], __ldg(&obw1[i * DIM + k]), v);
        hB[k] = selu_f(v);
    }
    __syncthreads();

    if (tid < 21) {
        float v = __ldg(&oab2[tid]);
        #pragma unroll 8
        for (int i = 0; i < DIM; ++i) v = fmaf(hA[i], __ldg(&oaw2[i * 21 + tid]), v);
        out[b * 21 + tid] = 1.f / (1.f + __expf(-v));
    } else if (tid >= 64 && tid < 104) {
        const int k = tid - 64;
        float v = __ldg(&obb2[k]);
        #pragma unroll 8
        for (int i = 0; i < DIM; ++i) v = fmaf(hB[i], __ldg(&obw2[i * 40 + k]), v);
        out[NBAGS * 21 + b * 40 + k] = 1.f / (1.f + __expf(-v));
    }
}

extern "C" void kernel_launch(void* const* d_in, const int* in_sizes, int n_in,
                              void* d_out, int out_size)
{
    (void)in_sizes; (void)n_in; (void)out_size;
    const float* x    = (const float*)d_in[0];
    const int*   nper = (const int*)  d_in[1];
    const float* w1   = (const float*)d_in[2];
    const float* b1   = (const float*)d_in[3];
    const float* w2   = (const float*)d_in[4];
    const float* b2   = (const float*)d_in[5];
    const float* aw1  = (const float*)d_in[6];
    const float* ab1  = (const float*)d_in[7];
    const float* aw2  = (const float*)d_in[8];
    const float* ab2  = (const float*)d_in[9];
    const float* aw3  = (const float*)d_in[10];
    const float* ab3  = (const float*)d_in[11];
    const float* oaw1 = (const float*)d_in[12];
    const float* oab1 = (const float*)d_in[13];
    const float* oaw2 = (const float*)d_in[14];
    const float* oab2 = (const float*)d_in[15];
    const float* obw1 = (const float*)d_in[16];
    const float* obb1 = (const float*)d_in[17];
    const float* obw2 = (const float*)d_in[18];
    const float* obb2 = (const float*)d_in[19];

    static int init = 0;
    if (!init) {
        cudaFuncSetAttribute(seq_kernel,
                             cudaFuncAttributeMaxDynamicSharedMemorySize,
                             SM_TOTAL);
        init = 1;
    }

    pack_kernel<<<1, 32>>>(w1, w2);
    nop_kernel<<<1, 32>>>();
    nop_kernel<<<1, 32>>>();
    seq_kernel<<<NBLK, 256, SM_TOTAL>>>(
        x, b1, b2, aw1, ab1, aw2, ab2, aw3, ab3);
    bag_all_kernel<<<NBAGS, 1024>>>(
        nper, oaw1, oab1, oaw2, oab2, obw1, obb1, obw2, obb2, (float*)d_out);
}

// round 15
// speedup vs baseline: 1.0488x; 1.0488x over previous
#include <cuda_runtime.h>
#include <cuda_bf16.h>
#include <math.h>

#define NSEQ 250000
#define DIM 32
#define NBAGS 100
#define TSEQ 16                 /* 2 seqs per warp, stacked */
#define NBLK (NSEQ / TSEQ)      /* 15625 */
#define XROW 24
#define H1ROW 40
#define WXROWS 80               /* stacked x rows per warp */
#define WHROWS 74               /* stacked h1 rows per warp */

/* dynamic smem (bytes) */
#define XS_OFF 0                                    /* 8*80*24*2 = 30720 */
#define H1_OFF 30720                                /* 8*74*40*2 = 47360 */
#define ES_OFF (30720 + 47360)                      /* 78080 */
#define SM_TOTAL (ES_OFF + TSEQ * DIM * 4)          /* 80128 */

__device__ float g_embed[NSEQ * DIM];
__device__ float g_scores[NSEQ];
__device__ uint4 d_frag1[6][2][32];
__device__ uint4 d_frag2[8][2][32];

__device__ __forceinline__ float selu_f(float x) {
    const float s = 1.0507009873554805f;
    const float sa = 1.0507009873554805f * 1.6732632423543772f;
    float p = fmaxf(x, 0.f), m = fminf(x, 0.f);
    return fmaf(s, p, sa * (__expf(m) - 1.f));
}
__device__ __forceinline__ unsigned pk(float lo, float hi) {
    __nv_bfloat162 t = __floats2bfloat162_rn(lo, hi);
    return *reinterpret_cast<unsigned*>(&t);
}
__device__ __forceinline__ void mma16(float* c, unsigned a0, unsigned a1,
                                      unsigned a2, unsigned a3,
                                      unsigned b0, unsigned b1) {
    asm volatile(
        "mma.sync.aligned.m16n8k16.row.col.f32.bf16.bf16.f32 "
        "{%0,%1,%2,%3}, {%4,%5,%6,%7}, {%8,%9}, {%0,%1,%2,%3};\n"
        : "+f"(c[0]), "+f"(c[1]), "+f"(c[2]), "+f"(c[3])
        : "r"(a0), "r"(a1), "r"(a2), "r"(a3), "r"(b0), "r"(b1));
}
__device__ __forceinline__ void ldsm4(unsigned& r0, unsigned& r1,
                                      unsigned& r2, unsigned& r3, unsigned a) {
    asm volatile("ldmatrix.sync.aligned.m8n8.x4.shared.b16 {%0,%1,%2,%3}, [%4];"
                 : "=r"(r0), "=r"(r1), "=r"(r2), "=r"(r3) : "r"(a));
}
__device__ __forceinline__ float w1pad(const float* __restrict__ w1, int kp, int n) {
    const int tap = kp / 24, ch = kp - tap * 24;
    return (ch < 20) ? w1[(tap * 20 + ch) * 32 + n] : 0.f;
}

__global__ void pack_kernel(const float* __restrict__ w1,
                            const float* __restrict__ w2)
{
    const int lane = threadIdx.x & 31;
    if (threadIdx.x >= 32) return;
    const int lr = lane >> 2, lc = lane & 3;
    for (int ks = 0; ks < 6; ++ks)
        for (int ntp = 0; ntp < 2; ++ntp) {
            const int kp = 16 * ks + 2 * lc;
            const int n0 = 16 * ntp + lr, n1 = n0 + 8;
            uint4 v;
            v.x = pk(w1pad(w1, kp, n0),     w1pad(w1, kp + 1, n0));
            v.y = pk(w1pad(w1, kp + 8, n0), w1pad(w1, kp + 9, n0));
            v.z = pk(w1pad(w1, kp, n1),     w1pad(w1, kp + 1, n1));
            v.w = pk(w1pad(w1, kp + 8, n1), w1pad(w1, kp + 9, n1));
            d_frag1[ks][ntp][lane] = v;
        }
    for (int ks = 0; ks < 8; ++ks)
        for (int ntp = 0; ntp < 2; ++ntp) {
            const int k0 = 16 * ks + 2 * lc;
            const int n0 = 16 * ntp + lr, n1 = n0 + 8;
            uint4 v;
            v.x = pk(w2[k0 * 32 + n0],       w2[(k0 + 1) * 32 + n0]);
            v.y = pk(w2[(k0 + 8) * 32 + n0], w2[(k0 + 9) * 32 + n0]);
            v.z = pk(w2[k0 * 32 + n1],       w2[(k0 + 1) * 32 + n1]);
            v.w = pk(w2[(k0 + 8) * 32 + n1], w2[(k0 + 9) * 32 + n1]);
            d_frag2[ks][ntp][lane] = v;
        }
}

// ---------------------------------------------------------------------------
// seq_kernel: warp owns seqs (w, w+8) stacked; 5+5 m16 tiles; warp-local sync
// ---------------------------------------------------------------------------
__global__ __launch_bounds__(256, 2) void seq_kernel(
    const float* __restrict__ x,
    const float* __restrict__ b1, const float* __restrict__ b2,
    const float* __restrict__ aw1, const float* __restrict__ ab1,
    const float* __restrict__ aw2, const float* __restrict__ ab2,
    const float* __restrict__ aw3, const float* __restrict__ ab3)
{
    extern __shared__ char sm[];
    __nv_bfloat16* xs  = (__nv_bfloat16*)(sm + XS_OFF);
    __nv_bfloat16* h1s = (__nv_bfloat16*)(sm + H1_OFF);
    float (*es_s)[DIM] = (float(*)[DIM])(sm + ES_OFF);

    const int tid = threadIdx.x;
    const int warp = tid >> 5, lane = tid & 31;
    const int lr = lane >> 2, lc = lane & 3;
    const int rowq = lane & 15;
    const int khalf = (lane >> 4) * 8;

    // ---- stage x: 640 rows -> warp-stacked padded regions ----
    {
        const float4* xg = (const float4*)(x + (long)blockIdx.x * (TSEQ * 40 * 20));
        for (int r = tid; r < TSEQ * 40; r += 256) {
            const int sg = r / 40, t = r - sg * 40;
            const int w = sg & 7, h = sg >> 3;
            const float4 v0 = xg[r * 5], v1 = xg[r * 5 + 1], v2 = xg[r * 5 + 2];
            const float4 v3 = xg[r * 5 + 3], v4 = xg[r * 5 + 4];
            __nv_bfloat16* d = xs + (w * WXROWS + h * 40 + t) * XROW;
            *(uint4*)d = make_uint4(pk(v0.x, v0.y), pk(v0.z, v0.w),
                                    pk(v1.x, v1.y), pk(v1.z, v1.w));
            *(uint4*)(d + 8) = make_uint4(pk(v2.x, v2.y), pk(v2.z, v2.w),
                                          pk(v3.x, v3.y), pk(v3.z, v3.w));
            *(uint2*)(d + 16) = make_uint2(pk(v4.x, v4.y), pk(v4.z, v4.w));
            *(uint2*)(d + 20) = make_uint2(0u, 0u);
        }
    }

    // ---- conv1 fragments + bias ----
    unsigned B1r[6][4][2];
    #pragma unroll
    for (int ks = 0; ks < 6; ++ks) {
        const uint4 v0 = d_frag1[ks][0][lane];
        const uint4 v1 = d_frag1[ks][1][lane];
        B1r[ks][0][0] = v0.x; B1r[ks][0][1] = v0.y;
        B1r[ks][1][0] = v0.z; B1r[ks][1][1] = v0.w;
        B1r[ks][2][0] = v1.x; B1r[ks][2][1] = v1.y;
        B1r[ks][3][0] = v1.z; B1r[ks][3][1] = v1.w;
    }
    float bias1[4][2];
    #pragma unroll
    for (int nt = 0; nt < 4; ++nt) {
        bias1[nt][0] = __ldg(&b1[nt * 8 + 2 * lc]);
        bias1[nt][1] = __ldg(&b1[nt * 8 + 2 * lc + 1]);
    }
    __syncthreads();

    const unsigned xw_s = (unsigned)__cvta_generic_to_shared(xs + warp * WXROWS * XROW);
    const unsigned hw_s = (unsigned)__cvta_generic_to_shared(h1s + warp * WHROWS * H1ROW);
    __nv_bfloat16* Hw = h1s + warp * WHROWS * H1ROW;

    // ---- conv1: 5 tiles over 74 stacked rows (boundary 37) ----
    #pragma unroll
    for (int tile = 0; tile < 5; ++tile) {
        int r = tile * 16 + rowq;
        int rc = r > 73 ? 73 : r;
        const int fr = rc + (rc >= 37 ? 3 : 0);
        const unsigned abase = xw_s + (fr * XROW + khalf) * 2;
        float acc[4][4];
        #pragma unroll
        for (int nt = 0; nt < 4; ++nt) {
            acc[nt][0] = bias1[nt][0]; acc[nt][1] = bias1[nt][1];
            acc[nt][2] = bias1[nt][0]; acc[nt][3] = bias1[nt][1];
        }
        #pragma unroll
        for (int ks = 0; ks < 6; ++ks) {
            unsigned a0, a1, a2, a3;
            ldsm4(a0, a1, a2, a3, abase + ks * 32);
            #pragma unroll
            for (int nt = 0; nt < 4; ++nt)
                mma16(acc[nt], a0, a1, a2, a3, B1r[ks][nt][0], B1r[ks][nt][1]);
        }
        const int r0 = tile * 16 + lr;              // <= 71, always valid
        int r1 = r0 + 8; if (r1 > 73) r1 = 73;      // dup stores benign
        #pragma unroll
        for (int nt = 0; nt < 4; ++nt) {
            const int col = nt * 8 + 2 * lc;
            *(unsigned*)(Hw + r0 * H1ROW + col) =
                pk(selu_f(acc[nt][0]), selu_f(acc[nt][1]));
            *(unsigned*)(Hw + r1 * H1ROW + col) =
                pk(selu_f(acc[nt][2]), selu_f(acc[nt][3]));
        }
    }

    // ---- conv2 fragments + bias ----
    unsigned B2r[8][4][2];
    #pragma unroll
    for (int ks = 0; ks < 8; ++ks) {
        const uint4 v0 = d_frag2[ks][0][lane];
        const uint4 v1 = d_frag2[ks][1][lane];
        B2r[ks][0][0] = v0.x; B2r[ks][0][1] = v0.y;
        B2r[ks][1][0] = v0.z; B2r[ks][1][1] = v0.w;
        B2r[ks][2][0] = v1.x; B2r[ks][2][1] = v1.y;
        B2r[ks][3][0] = v1.z; B2r[ks][3][1] = v1.w;
    }
    float bias2[4][2];
    #pragma unroll
    for (int nt = 0; nt < 4; ++nt) {
        bias2[nt][0] = __ldg(&b2[nt * 8 + 2 * lc]);
        bias2[nt][1] = __ldg(&b2[nt * 8 + 2 * lc + 1]);
    }
    __syncwarp();   // h1 for this warp's seqs written only by this warp

    // ---- conv2: 5 tiles over 68 stacked rows (boundary 34) ----
    float vmA[4][2], vmB[4][2];
    #pragma unroll
    for (int nt = 0; nt < 4; ++nt) {
        vmA[nt][0] = -INFINITY; vmA[nt][1] = -INFINITY;
        vmB[nt][0] = -INFINITY; vmB[nt][1] = -INFINITY;
    }

    #pragma unroll
    for (int tile = 0; tile < 5; ++tile) {
        int r = tile * 16 + rowq;
        int rc = r > 67 ? 67 : r;
        const int fr = rc + (rc >= 34 ? 3 : 0);
        const unsigned abase = hw_s + (fr * H1ROW + khalf) * 2;
        float acc[4][4];
        #pragma unroll
        for (int nt = 0; nt < 4; ++nt) {
            acc[nt][0] = bias2[nt][0]; acc[nt][1] = bias2[nt][1];
            acc[nt][2] = bias2[nt][0]; acc[nt][3] = bias2[nt][1];
        }
        #pragma unroll
        for (int ks = 0; ks < 8; ++ks) {
            unsigned a0, a1, a2, a3;
            ldsm4(a0, a1, a2, a3,
                  abase + ((ks >> 1) * H1ROW + (ks & 1) * 16) * 2);
            #pragma unroll
            for (int nt = 0; nt < 4; ++nt)
                mma16(acc[nt], a0, a1, a2, a3, B2r[ks][nt][0], B2r[ks][nt][1]);
        }
        #pragma unroll
        for (int nt = 0; nt < 4; ++nt) {
            if (tile < 2) {                                    // rows 0..31: A
                vmA[nt][0] = fmaxf(vmA[nt][0], fmaxf(acc[nt][0], acc[nt][2]));
                vmA[nt][1] = fmaxf(vmA[nt][1], fmaxf(acc[nt][1], acc[nt][3]));
            } else if (tile == 2) {                            // rows 32+lr / 40+lr
                if (lr < 2) {                                  // rows 32,33: A
                    vmA[nt][0] = fmaxf(vmA[nt][0], acc[nt][0]);
                    vmA[nt][1] = fmaxf(vmA[nt][1], acc[nt][1]);
                } else {                                       // rows 34..39: B
                    vmB[nt][0] = fmaxf(vmB[nt][0], acc[nt][0]);
                    vmB[nt][1] = fmaxf(vmB[nt][1], acc[nt][1]);
                }
                vmB[nt][0] = fmaxf(vmB[nt][0], acc[nt][2]);    // rows 40..47: B
                vmB[nt][1] = fmaxf(vmB[nt][1], acc[nt][3]);
            } else {                                           // rows 48..67+: B
                vmB[nt][0] = fmaxf(vmB[nt][0], fmaxf(acc[nt][0], acc[nt][2]));
                vmB[nt][1] = fmaxf(vmB[nt][1], fmaxf(acc[nt][1], acc[nt][3]));
            }
        }
        if (tile == 2) {   // seq A complete: reduce + store, free vmA
            #pragma unroll
            for (int nt = 0; nt < 4; ++nt)
                #pragma unroll
                for (int j = 0; j < 2; ++j) {
                    float v = vmA[nt][j];
                    v = fmaxf(v, __shfl_xor_sync(0xffffffffu, v, 4));
                    v = fmaxf(v, __shfl_xor_sync(0xffffffffu, v, 8));
                    v = fmaxf(v, __shfl_xor_sync(0xffffffffu, v, 16));
                    vmA[nt][j] = v;
                }
            if (lane < 4)
                #pragma unroll
                for (int nt = 0; nt < 4; ++nt) {
                    es_s[warp][nt * 8 + 2 * lane]     = selu_f(vmA[nt][0]);
                    es_s[warp][nt * 8 + 2 * lane + 1] = selu_f(vmA[nt][1]);
                }
            __syncwarp();
            g_embed[((long)blockIdx.x * TSEQ + warp) * DIM + lane] = es_s[warp][lane];
        }
    }
    // seq B reduce + store
    #pragma unroll
    for (int nt = 0; nt < 4; ++nt)
        #pragma unroll
        for (int j = 0; j < 2; ++j) {
            float v = vmB[nt][j];
            v = fmaxf(v, __shfl_xor_sync(0xffffffffu, v, 4));
            v = fmaxf(v, __shfl_xor_sync(0xffffffffu, v, 8));
            v = fmaxf(v, __shfl_xor_sync(0xffffffffu, v, 16));
            vmB[nt][j] = v;
        }
    if (lane < 4)
        #pragma unroll
        for (int nt = 0; nt < 4; ++nt) {
            es_s[warp + 8][nt * 8 + 2 * lane]     = selu_f(vmB[nt][0]);
            es_s[warp + 8][nt * 8 + 2 * lane + 1] = selu_f(vmB[nt][1]);
        }
    __syncwarp();
    g_embed[((long)blockIdx.x * TSEQ + warp + 8) * DIM + lane] = es_s[warp + 8][lane];

    // ---- attention MLP: weights hoisted once, two seqs per warp ----
    {
        const int j = lane;
        float W1[DIM], W2[DIM];
        #pragma unroll 8
        for (int i = 0; i < DIM; ++i) W1[i] = __ldg(&aw1[i * DIM + j]);
        #pragma unroll 8
        for (int i = 0; i < DIM; ++i) W2[i] = __ldg(&aw2[i * DIM + j]);
        const float w3  = __ldg(&aw3[j]);
        const float bb1 = __ldg(&ab1[j]);
        const float bb2 = __ldg(&ab2[j]);
        const float bb3 = __ldg(&ab3[0]);

        #pragma unroll
        for (int h = 0; h < 2; ++h) {
            const int srow = warp + 8 * h;
            const float* e = es_s[srow];
            float a1v = bb1;
            #pragma unroll
            for (int i = 0; i < DIM; ++i)
                a1v = fmaf(e[i], W1[i], a1v);
            a1v = selu_f(a1v);
            float a2v = bb2;
            #pragma unroll
            for (int i = 0; i < DIM; ++i)
                a2v = fmaf(__shfl_sync(0xffffffffu, a1v, i), W2[i], a2v);
            a2v = selu_f(a2v);
            float sc = a2v * w3;
            #pragma unroll
            for (int o = 16; o > 0; o >>= 1)
                sc += __shfl_xor_sync(0xffffffffu, sc, o);
            if (j == 0)
                g_scores[(long)blockIdx.x * TSEQ + srow] = sc + bb3;
        }
    }
}

// ---------------------------------------------------------------------------
// bag pipeline (unchanged, validated)
// ---------------------------------------------------------------------------
__global__ __launch_bounds__(1024) void bag_all_kernel(
    const int* __restrict__ nper,
    const float* __restrict__ oaw1, const float* __restrict__ oab1,
    const float* __restrict__ oaw2, const float* __restrict__ oab2,
    const float* __restrict__ obw1, const float* __restrict__ obb1,
    const float* __restrict__ obw2, const float* __restrict__ obb2,
    float* __restrict__ out)
{
    __shared__ float red[1024];
    __shared__ float part[32][33];
    __shared__ float pooled[DIM], hA[DIM], hB[DIM];
    __shared__ int s_off, s_cnt;
    __shared__ float s_mx, s_dn;

    const int tid = threadIdx.x, b = blockIdx.x;
    if (tid == 0) {
        int off = 0;
        for (int i = 0; i < b; ++i) off += nper[i];
        s_off = off; s_cnt = nper[b];
    }
    __syncthreads();
    const int off = s_off, cnt = s_cnt;

    float lm = -INFINITY;
    for (int i = tid; i < cnt; i += 1024) lm = fmaxf(lm, g_scores[off + i]);
    red[tid] = lm; __syncthreads();
    for (int s = 512; s > 0; s >>= 1) {
        if (tid < s) red[tid] = fmaxf(red[tid], red[tid + s]);
        __syncthreads();
    }
    if (tid == 0) s_mx = red[0];
    __syncthreads();
    const float mx = s_mx;

    float ls = 0.f;
    for (int i = tid; i < cnt; i += 1024) ls += __expf(g_scores[off + i] - mx);
    red[tid] = ls; __syncthreads();
    for (int s = 512; s > 0; s >>= 1) {
        if (tid < s) red[tid] += red[tid + s];
        __syncthreads();
    }
    if (tid == 0) s_dn = red[0];
    __syncthreads();
    const float dn = s_dn;

    const int g = tid >> 5, c = tid & 31;
    float acc = 0.f;
    for (int p = g; p < cnt; p += 32) {
        const float wgt = __expf(g_scores[off + p] - mx);
        acc = fmaf(wgt, g_embed[(long)(off + p) * DIM + c], acc);
    }
    part[g][c] = acc;
    __syncthreads();
    if (tid < DIM) {
        float s = 0.f;
        #pragma unroll
        for (int gg = 0; gg < 32; ++gg) s += part[gg][tid];
        pooled[tid] = s / dn;
    }
    __syncthreads();

    if (tid < DIM) {
        float v = __ldg(&oab1[tid]);
        #pragma unroll 8
        for (int i = 0; i < DIM; ++i) v = fmaf(pooled[i], __ldg(&oaw1[i * DIM + tid]), v);
        hA[tid] = selu_f(v);
    } else if (tid < 2 * DIM) {
        const int k = tid - DIM;
        float v = __ldg(&obb1[k]);
        #pragma unroll 8
        for (int i = 0; i < DIM; ++i) v = fmaf(pooled[i], __ldg(&obw1[i * DIM + k]), v);
        hB[k] = selu_f(v);
    }
    __syncthreads();

    if (tid < 21) {
        float v = __ldg(&oab2[tid]);
        #pragma unroll 8
        for (int i = 0; i < DIM; ++i) v = fmaf(hA[i], __ldg(&oaw2[i * 21 + tid]), v);
        out[b * 21 + tid] = 1.f / (1.f + __expf(-v));
    } else if (tid >= 64 && tid < 104) {
        const int k = tid - 64;
        float v = __ldg(&obb2[k]);
        #pragma unroll 8
        for (int i = 0; i < DIM; ++i) v = fmaf(hB[i], __ldg(&obw2[i * 40 + k]), v);
        out[NBAGS * 21 + b * 40 + k] = 1.f / (1.f + __expf(-v));
    }
}

extern "C" void kernel_launch(void* const* d_in, const int* in_sizes, int n_in,
                              void* d_out, int out_size)
{
    (void)in_sizes; (void)n_in; (void)out_size;
    const float* x    = (const float*)d_in[0];
    const int*   nper = (const int*)  d_in[1];
    const float* w1   = (const float*)d_in[2];
    const float* b1   = (const float*)d_in[3];
    const float* w2   = (const float*)d_in[4];
    const float* b2   = (const float*)d_in[5];
    const float* aw1  = (const float*)d_in[6];
    const float* ab1  = (const float*)d_in[7];
    const float* aw2  = (const float*)d_in[8];
    const float* ab2  = (const float*)d_in[9];
    const float* aw3  = (const float*)d_in[10];
    const float* ab3  = (const float*)d_in[11];
    const float* oaw1 = (const float*)d_in[12];
    const float* oab1 = (const float*)d_in[13];
    const float* oaw2 = (const float*)d_in[14];
    const float* oab2 = (const float*)d_in[15];
    const float* obw1 = (const float*)d_in[16];
    const float* obb1 = (const float*)d_in[17];
    const float* obw2 = (const float*)d_in[18];
    const float* obb2 = (const float*)d_in[19];

    static int init = 0;
    if (!init) {
        cudaFuncSetAttribute(seq_kernel,
                             cudaFuncAttributeMaxDynamicSharedMemorySize,
                             SM_TOTAL);
        init = 1;
    }

    pack_kernel<<<1, 32>>>(w1, w2);
    seq_kernel<<<NBLK, 256, SM_TOTAL>>>(
        x, b1, b2, aw1, ab1, aw2, ab2, aw3, ab3);
    bag_all_kernel<<<NBAGS, 1024>>>(
        nper, oaw1, oab1, oaw2, oab2, obw1, obb1, obw2, obb2, (float*)d_out);
}

// round 16
// speedup vs baseline: 1.1370x; 1.0841x over previous
#include <cuda_runtime.h>
#include <cuda_bf16.h>
#include <math.h>

#define NSEQ 250000
#define DIM 32
#define NBAGS 100
#define TSEQ 16                 /* 2 seqs per warp, stacked */
#define NBLK (NSEQ / TSEQ)      /* 15625 */
#define XROW 24
#define H1ROW 40
#define WXROWS 80               /* stacked x rows per warp */
#define WHROWS 74               /* stacked h1 rows per warp */

/* dynamic smem (bytes) */
#define XS_OFF 0                                    /* 8*80*24*2 = 30720 */
#define H1_OFF 30720                                /* 8*74*40*2 = 47360 */
#define ES_OFF (30720 + 47360)                      /* 78080 */
#define SM_TOTAL (ES_OFF + TSEQ * DIM * 4)          /* 80128 */

__device__ float g_embed[NSEQ * DIM];
__device__ float g_scores[NSEQ];
__device__ uint4 d_frag1[6][2][32];
__device__ uint4 d_frag2[8][2][32];

__device__ __forceinline__ float selu_f(float x) {
    const float s = 1.0507009873554805f;
    const float sa = 1.0507009873554805f * 1.6732632423543772f;
    float p = fmaxf(x, 0.f), m = fminf(x, 0.f);
    return fmaf(s, p, sa * (__expf(m) - 1.f));
}
__device__ __forceinline__ unsigned pk(float lo, float hi) {
    __nv_bfloat162 t = __floats2bfloat162_rn(lo, hi);
    return *reinterpret_cast<unsigned*>(&t);
}
__device__ __forceinline__ void mma16(float* c, unsigned a0, unsigned a1,
                                      unsigned a2, unsigned a3,
                                      unsigned b0, unsigned b1) {
    asm volatile(
        "mma.sync.aligned.m16n8k16.row.col.f32.bf16.bf16.f32 "
        "{%0,%1,%2,%3}, {%4,%5,%6,%7}, {%8,%9}, {%0,%1,%2,%3};\n"
        : "+f"(c[0]), "+f"(c[1]), "+f"(c[2]), "+f"(c[3])
        : "r"(a0), "r"(a1), "r"(a2), "r"(a3), "r"(b0), "r"(b1));
}
__device__ __forceinline__ void ldsm4(unsigned& r0, unsigned& r1,
                                      unsigned& r2, unsigned& r3, unsigned a) {
    asm volatile("ldmatrix.sync.aligned.m8n8.x4.shared.b16 {%0,%1,%2,%3}, [%4];"
                 : "=r"(r0), "=r"(r1), "=r"(r2), "=r"(r3) : "r"(a));
}
__device__ __forceinline__ float w1pad(const float* __restrict__ w1, int kp, int n) {
    const int tap = kp / 24, ch = kp - tap * 24;
    return (ch < 20) ? w1[(tap * 20 + ch) * 32 + n] : 0.f;
}

__global__ void pack_kernel(const float* __restrict__ w1,
                            const float* __restrict__ w2)
{
    const int lane = threadIdx.x & 31;
    if (threadIdx.x >= 32) return;
    const int lr = lane >> 2, lc = lane & 3;
    for (int ks = 0; ks < 6; ++ks)
        for (int ntp = 0; ntp < 2; ++ntp) {
            const int kp = 16 * ks + 2 * lc;
            const int n0 = 16 * ntp + lr, n1 = n0 + 8;
            uint4 v;
            v.x = pk(w1pad(w1, kp, n0),     w1pad(w1, kp + 1, n0));
            v.y = pk(w1pad(w1, kp + 8, n0), w1pad(w1, kp + 9, n0));
            v.z = pk(w1pad(w1, kp, n1),     w1pad(w1, kp + 1, n1));
            v.w = pk(w1pad(w1, kp + 8, n1), w1pad(w1, kp + 9, n1));
            d_frag1[ks][ntp][lane] = v;
        }
    for (int ks = 0; ks < 8; ++ks)
        for (int ntp = 0; ntp < 2; ++ntp) {
            const int k0 = 16 * ks + 2 * lc;
            const int n0 = 16 * ntp + lr, n1 = n0 + 8;
            uint4 v;
            v.x = pk(w2[k0 * 32 + n0],       w2[(k0 + 1) * 32 + n0]);
            v.y = pk(w2[(k0 + 8) * 32 + n0], w2[(k0 + 9) * 32 + n0]);
            v.z = pk(w2[k0 * 32 + n1],       w2[(k0 + 1) * 32 + n1]);
            v.w = pk(w2[(k0 + 8) * 32 + n1], w2[(k0 + 9) * 32 + n1]);
            d_frag2[ks][ntp][lane] = v;
        }
}

// ---------------------------------------------------------------------------
// seq_kernel: warp owns seqs (w, w+8) stacked; 5+5 m16 tiles; warp-local sync
// ---------------------------------------------------------------------------
__global__ __launch_bounds__(256, 2) void seq_kernel(
    const float* __restrict__ x,
    const float* __restrict__ b1, const float* __restrict__ b2,
    const float* __restrict__ aw1, const float* __restrict__ ab1,
    const float* __restrict__ aw2, const float* __restrict__ ab2,
    const float* __restrict__ aw3, const float* __restrict__ ab3)
{
    extern __shared__ char sm[];
    __nv_bfloat16* xs  = (__nv_bfloat16*)(sm + XS_OFF);
    __nv_bfloat16* h1s = (__nv_bfloat16*)(sm + H1_OFF);
    float (*es_s)[DIM] = (float(*)[DIM])(sm + ES_OFF);

    const int tid = threadIdx.x;
    const int warp = tid >> 5, lane = tid & 31;
    const int lr = lane >> 2, lc = lane & 3;
    const int rowq = lane & 15;
    const int khalf = (lane >> 4) * 8;

    // ---- stage x: 640 rows -> warp-stacked padded regions ----
    {
        const float4* xg = (const float4*)(x + (long)blockIdx.x * (TSEQ * 40 * 20));
        for (int r = tid; r < TSEQ * 40; r += 256) {
            const int sg = r / 40, t = r - sg * 40;
            const int w = sg & 7, h = sg >> 3;
            const float4 v0 = xg[r * 5], v1 = xg[r * 5 + 1], v2 = xg[r * 5 + 2];
            const float4 v3 = xg[r * 5 + 3], v4 = xg[r * 5 + 4];
            __nv_bfloat16* d = xs + (w * WXROWS + h * 40 + t) * XROW;
            *(uint4*)d = make_uint4(pk(v0.x, v0.y), pk(v0.z, v0.w),
                                    pk(v1.x, v1.y), pk(v1.z, v1.w));
            *(uint4*)(d + 8) = make_uint4(pk(v2.x, v2.y), pk(v2.z, v2.w),
                                          pk(v3.x, v3.y), pk(v3.z, v3.w));
            *(uint2*)(d + 16) = make_uint2(pk(v4.x, v4.y), pk(v4.z, v4.w));
            *(uint2*)(d + 20) = make_uint2(0u, 0u);
        }
    }

    // ---- conv1 fragments + bias ----
    unsigned B1r[6][4][2];
    #pragma unroll
    for (int ks = 0; ks < 6; ++ks) {
        const uint4 v0 = d_frag1[ks][0][lane];
        const uint4 v1 = d_frag1[ks][1][lane];
        B1r[ks][0][0] = v0.x; B1r[ks][0][1] = v0.y;
        B1r[ks][1][0] = v0.z; B1r[ks][1][1] = v0.w;
        B1r[ks][2][0] = v1.x; B1r[ks][2][1] = v1.y;
        B1r[ks][3][0] = v1.z; B1r[ks][3][1] = v1.w;
    }
    float bias1[4][2];
    #pragma unroll
    for (int nt = 0; nt < 4; ++nt) {
        bias1[nt][0] = __ldg(&b1[nt * 8 + 2 * lc]);
        bias1[nt][1] = __ldg(&b1[nt * 8 + 2 * lc + 1]);
    }
    __syncthreads();

    const unsigned xw_s = (unsigned)__cvta_generic_to_shared(xs + warp * WXROWS * XROW);
    const unsigned hw_s = (unsigned)__cvta_generic_to_shared(h1s + warp * WHROWS * H1ROW);
    __nv_bfloat16* Hw = h1s + warp * WHROWS * H1ROW;

    // ---- conv1: 5 tiles over 74 stacked rows (boundary 37) ----
    #pragma unroll
    for (int tile = 0; tile < 5; ++tile) {
        int r = tile * 16 + rowq;
        int rc = r > 73 ? 73 : r;
        const int fr = rc + (rc >= 37 ? 3 : 0);
        const unsigned abase = xw_s + (fr * XROW + khalf) * 2;
        float acc[4][4];
        #pragma unroll
        for (int nt = 0; nt < 4; ++nt) {
            acc[nt][0] = bias1[nt][0]; acc[nt][1] = bias1[nt][1];
            acc[nt][2] = bias1[nt][0]; acc[nt][3] = bias1[nt][1];
        }
        #pragma unroll
        for (int ks = 0; ks < 6; ++ks) {
            unsigned a0, a1, a2, a3;
            ldsm4(a0, a1, a2, a3, abase + ks * 32);
            #pragma unroll
            for (int nt = 0; nt < 4; ++nt)
                mma16(acc[nt], a0, a1, a2, a3, B1r[ks][nt][0], B1r[ks][nt][1]);
        }
        const int r0 = tile * 16 + lr;              // <= 71, always valid
        int r1 = r0 + 8; if (r1 > 73) r1 = 73;      // dup stores benign
        #pragma unroll
        for (int nt = 0; nt < 4; ++nt) {
            const int col = nt * 8 + 2 * lc;
            *(unsigned*)(Hw + r0 * H1ROW + col) =
                pk(selu_f(acc[nt][0]), selu_f(acc[nt][1]));
            *(unsigned*)(Hw + r1 * H1ROW + col) =
                pk(selu_f(acc[nt][2]), selu_f(acc[nt][3]));
        }
    }

    // ---- conv2 fragments + bias ----
    unsigned B2r[8][4][2];
    #pragma unroll
    for (int ks = 0; ks < 8; ++ks) {
        const uint4 v0 = d_frag2[ks][0][lane];
        const uint4 v1 = d_frag2[ks][1][lane];
        B2r[ks][0][0] = v0.x; B2r[ks][0][1] = v0.y;
        B2r[ks][1][0] = v0.z; B2r[ks][1][1] = v0.w;
        B2r[ks][2][0] = v1.x; B2r[ks][2][1] = v1.y;
        B2r[ks][3][0] = v1.z; B2r[ks][3][1] = v1.w;
    }
    float bias2[4][2];
    #pragma unroll
    for (int nt = 0; nt < 4; ++nt) {
        bias2[nt][0] = __ldg(&b2[nt * 8 + 2 * lc]);
        bias2[nt][1] = __ldg(&b2[nt * 8 + 2 * lc + 1]);
    }
    __syncwarp();   // h1 for this warp's seqs written only by this warp

    // ---- conv2: 5 tiles over 68 stacked rows (boundary 34) ----
    float vmA[4][2], vmB[4][2];
    #pragma unroll
    for (int nt = 0; nt < 4; ++nt) {
        vmA[nt][0] = -INFINITY; vmA[nt][1] = -INFINITY;
        vmB[nt][0] = -INFINITY; vmB[nt][1] = -INFINITY;
    }

    #pragma unroll
    for (int tile = 0; tile < 5; ++tile) {
        int r = tile * 16 + rowq;
        int rc = r > 67 ? 67 : r;
        const int fr = rc + (rc >= 34 ? 3 : 0);
        const unsigned abase = hw_s + (fr * H1ROW + khalf) * 2;
        float acc[4][4];
        #pragma unroll
        for (int nt = 0; nt < 4; ++nt) {
            acc[nt][0] = bias2[nt][0]; acc[nt][1] = bias2[nt][1];
            acc[nt][2] = bias2[nt][0]; acc[nt][3] = bias2[nt][1];
        }
        #pragma unroll
        for (int ks = 0; ks < 8; ++ks) {
            unsigned a0, a1, a2, a3;
            ldsm4(a0, a1, a2, a3,
                  abase + ((ks >> 1) * H1ROW + (ks & 1) * 16) * 2);
            #pragma unroll
            for (int nt = 0; nt < 4; ++nt)
                mma16(acc[nt], a0, a1, a2, a3, B2r[ks][nt][0], B2r[ks][nt][1]);
        }
        #pragma unroll
        for (int nt = 0; nt < 4; ++nt) {
            if (tile < 2) {                                    // rows 0..31: A
                vmA[nt][0] = fmaxf(vmA[nt][0], fmaxf(acc[nt][0], acc[nt][2]));
                vmA[nt][1] = fmaxf(vmA[nt][1], fmaxf(acc[nt][1], acc[nt][3]));
            } else if (tile == 2) {                            // rows 32+lr / 40+lr
                if (lr < 2) {                                  // rows 32,33: A
                    vmA[nt][0] = fmaxf(vmA[nt][0], acc[nt][0]);
                    vmA[nt][1] = fmaxf(vmA[nt][1], acc[nt][1]);
                } else {                                       // rows 34..39: B
                    vmB[nt][0] = fmaxf(vmB[nt][0], acc[nt][0]);
                    vmB[nt][1] = fmaxf(vmB[nt][1], acc[nt][1]);
                }
                vmB[nt][0] = fmaxf(vmB[nt][0], acc[nt][2]);    // rows 40..47: B
                vmB[nt][1] = fmaxf(vmB[nt][1], acc[nt][3]);
            } else {                                           // rows 48..67+: B
                vmB[nt][0] = fmaxf(vmB[nt][0], fmaxf(acc[nt][0], acc[nt][2]));
                vmB[nt][1] = fmaxf(vmB[nt][1], fmaxf(acc[nt][1], acc[nt][3]));
            }
        }
        if (tile == 2) {   // seq A complete: reduce + store, free vmA
            #pragma unroll
            for (int nt = 0; nt < 4; ++nt)
                #pragma unroll
                for (int j = 0; j < 2; ++j) {
                    float v = vmA[nt][j];
                    v = fmaxf(v, __shfl_xor_sync(0xffffffffu, v, 4));
                    v = fmaxf(v, __shfl_xor_sync(0xffffffffu, v, 8));
                    v = fmaxf(v, __shfl_xor_sync(0xffffffffu, v, 16));
                    vmA[nt][j] = v;
                }
            if (lane < 4)
                #pragma unroll
                for (int nt = 0; nt < 4; ++nt) {
                    es_s[warp][nt * 8 + 2 * lane]     = selu_f(vmA[nt][0]);
                    es_s[warp][nt * 8 + 2 * lane + 1] = selu_f(vmA[nt][1]);
                }
            __syncwarp();
            g_embed[((long)blockIdx.x * TSEQ + warp) * DIM + lane] = es_s[warp][lane];
        }
    }
    // seq B reduce + store
    #pragma unroll
    for (int nt = 0; nt < 4; ++nt)
        #pragma unroll
        for (int j = 0; j < 2; ++j) {
            float v = vmB[nt][j];
            v = fmaxf(v, __shfl_xor_sync(0xffffffffu, v, 4));
            v = fmaxf(v, __shfl_xor_sync(0xffffffffu, v, 8));
            v = fmaxf(v, __shfl_xor_sync(0xffffffffu, v, 16));
            vmB[nt][j] = v;
        }
    if (lane < 4)
        #pragma unroll
        for (int nt = 0; nt < 4; ++nt) {
            es_s[warp + 8][nt * 8 + 2 * lane]     = selu_f(vmB[nt][0]);
            es_s[warp + 8][nt * 8 + 2 * lane + 1] = selu_f(vmB[nt][1]);
        }
    __syncwarp();
    g_embed[((long)blockIdx.x * TSEQ + warp + 8) * DIM + lane] = es_s[warp + 8][lane];

    // ---- attention MLP: warp handles its two seqs (per-iteration __ldg) ----
    #pragma unroll
    for (int h = 0; h < 2; ++h) {
        const int srow = warp + 8 * h;
        const float* e = es_s[srow];
        const int j = lane;
        float a1v = __ldg(&ab1[j]);
        #pragma unroll 8
        for (int i = 0; i < DIM; ++i)
            a1v = fmaf(e[i], __ldg(&aw1[i * DIM + j]), a1v);
        a1v = selu_f(a1v);
        float a2v = __ldg(&ab2[j]);
        #pragma unroll 8
        for (int i = 0; i < DIM; ++i)
            a2v = fmaf(__shfl_sync(0xffffffffu, a1v, i), __ldg(&aw2[i * DIM + j]), a2v);
        a2v = selu_f(a2v);
        float sc = a2v * __ldg(&aw3[j]);
        #pragma unroll
        for (int o = 16; o > 0; o >>= 1) sc += __shfl_xor_sync(0xffffffffu, sc, o);
        if (j == 0)
            g_scores[(long)blockIdx.x * TSEQ + srow] = sc + __ldg(&ab3[0]);
    }
}

// ---------------------------------------------------------------------------
// bag pipeline (unchanged, validated)
// ---------------------------------------------------------------------------
__global__ __launch_bounds__(1024) void bag_all_kernel(
    const int* __restrict__ nper,
    const float* __restrict__ oaw1, const float* __restrict__ oab1,
    const float* __restrict__ oaw2, const float* __restrict__ oab2,
    const float* __restrict__ obw1, const float* __restrict__ obb1,
    const float* __restrict__ obw2, const float* __restrict__ obb2,
    float* __restrict__ out)
{
    __shared__ float red[1024];
    __shared__ float part[32][33];
    __shared__ float pooled[DIM], hA[DIM], hB[DIM];
    __shared__ int s_off, s_cnt;
    __shared__ float s_mx, s_dn;

    const int tid = threadIdx.x, b = blockIdx.x;
    if (tid == 0) {
        int off = 0;
        for (int i = 0; i < b; ++i) off += nper[i];
        s_off = off; s_cnt = nper[b];
    }
    __syncthreads();
    const int off = s_off, cnt = s_cnt;

    float lm = -INFINITY;
    for (int i = tid; i < cnt; i += 1024) lm = fmaxf(lm, g_scores[off + i]);
    red[tid] = lm; __syncthreads();
    for (int s = 512; s > 0; s >>= 1) {
        if (tid < s) red[tid] = fmaxf(red[tid], red[tid + s]);
        __syncthreads();
    }
    if (tid == 0) s_mx = red[0];
    __syncthreads();
    const float mx = s_mx;

    float ls = 0.f;
    for (int i = tid; i < cnt; i += 1024) ls += __expf(g_scores[off + i] - mx);
    red[tid] = ls; __syncthreads();
    for (int s = 512; s > 0; s >>= 1) {
        if (tid < s) red[tid] += red[tid + s];
        __syncthreads();
    }
    if (tid == 0) s_dn = red[0];
    __syncthreads();
    const float dn = s_dn;

    const int g = tid >> 5, c = tid & 31;
    float acc = 0.f;
    for (int p = g; p < cnt; p += 32) {
        const float wgt = __expf(g_scores[off + p] - mx);
        acc = fmaf(wgt, g_embed[(long)(off + p) * DIM + c], acc);
    }
    part[g][c] = acc;
    __syncthreads();
    if (tid < DIM) {
        float s = 0.f;
        #pragma unroll
        for (int gg = 0; gg < 32; ++gg) s += part[gg][tid];
        pooled[tid] = s / dn;
    }
    __syncthreads();

    if (tid < DIM) {
        float v = __ldg(&oab1[tid]);
        #pragma unroll 8
        for (int i = 0; i < DIM; ++i) v = fmaf(pooled[i], __ldg(&oaw1[i * DIM + tid]), v);
        hA[tid] = selu_f(v);
    } else if (tid < 2 * DIM) {
        const int k = tid - DIM;
        float v = __ldg(&obb1[k]);
        #pragma unroll 8
        for (int i = 0; i < DIM; ++i) v = fmaf(pooled[i], __ldg(&obw1[i * DIM + k]), v);
        hB[k] = selu_f(v);
    }
    __syncthreads();

    if (tid < 21) {
        float v = __ldg(&oab2[tid]);
        #pragma unroll 8
        for (int i = 0; i < DIM; ++i) v = fmaf(hA[i], __ldg(&oaw2[i * 21 + tid]), v);
        out[b * 21 + tid] = 1.f / (1.f + __expf(-v));
    } else if (tid >= 64 && tid < 104) {
        const int k = tid - 64;
        float v = __ldg(&obb2[k]);
        #pragma unroll 8
        for (int i = 0; i < DIM; ++i) v = fmaf(hB[i], __ldg(&obw2[i * 40 + k]), v);
        out[NBAGS * 21 + b * 40 + k] = 1.f / (1.f + __expf(-v));
    }
}

extern "C" void kernel_launch(void* const* d_in, const int* in_sizes, int n_in,
                              void* d_out, int out_size)
{
    (void)in_sizes; (void)n_in; (void)out_size;
    const float* x    = (const float*)d_in[0];
    const int*   nper = (const int*)  d_in[1];
    const float* w1   = (const float*)d_in[2];
    const float* b1   = (const float*)d_in[3];
    const float* w2   = (const float*)d_in[4];
    const float* b2   = (const float*)d_in[5];
    const float* aw1  = (const float*)d_in[6];
    const float* ab1  = (const float*)d_in[7];
    const float* aw2  = (const float*)d_in[8];
    const float* ab2  = (const float*)d_in[9];
    const float* aw3  = (const float*)d_in[10];
    const float* ab3  = (const float*)d_in[11];
    const float* oaw1 = (const float*)d_in[12];
    const float* oab1 = (const float*)d_in[13];
    const float* oaw2 = (const float*)d_in[14];
    const float* oab2 = (const float*)d_in[15];
    const float* obw1 = (const float*)d_in[16];
    const float* obb1 = (const float*)d_in[17];
    const float* obw2 = (const float*)d_in[18];
    const float* obb2 = (const float*)d_in[19];

    static int init = 0;
    if (!init) {
        cudaFuncSetAttribute(seq_kernel,
                             cudaFuncAttributeMaxDynamicSharedMemorySize,
                             SM_TOTAL);
        init = 1;
    }

    pack_kernel<<<1, 32>>>(w1, w2);
    seq_kernel<<<NBLK, 256, SM_TOTAL>>>(
        x, b1, b2, aw1, ab1, aw2, ab2, aw3, ab3);
    bag_all_kernel<<<NBAGS, 1024>>>(
        nper, oaw1, oab1, oaw2, oab2, obw1, obb1, obw2, obb2, (float*)d_out);
}

// round 17
// speedup vs baseline: 1.1490x; 1.0106x over previous
#include <cuda_runtime.h>
#include <cuda_bf16.h>
#include <math.h>

#define NSEQ 250000
#define DIM 32
#define NBAGS 100
#define TSEQ 16                 /* 2 seqs per warp, stacked */
#define NBLK (NSEQ / TSEQ)      /* 15625 */
#define XROW 24
#define H1ROW 40
#define WXROWS 80               /* stacked x rows per warp */
#define WHROWS 74               /* stacked h1 rows per warp */

/* dynamic smem (bytes) */
#define XS_OFF 0                                    /* 8*80*24*2 = 30720 */
#define H1_OFF 30720                                /* 8*74*40*2 = 47360 */
#define ES_OFF (30720 + 47360)                      /* 78080 */
#define SM_TOTAL (ES_OFF + TSEQ * DIM * 4)          /* 80128 */

__device__ float g_embed[NSEQ * DIM];
__device__ float g_scores[NSEQ];
__device__ uint4 d_frag1[6][2][32];
__device__ uint4 d_frag2[8][2][32];

__device__ __forceinline__ float selu_f(float x) {
    const float s = 1.0507009873554805f;
    const float sa = 1.0507009873554805f * 1.6732632423543772f;
    float p = fmaxf(x, 0.f), m = fminf(x, 0.f);
    return fmaf(s, p, sa * (__expf(m) - 1.f));
}
__device__ __forceinline__ unsigned pk(float lo, float hi) {
    __nv_bfloat162 t = __floats2bfloat162_rn(lo, hi);
    return *reinterpret_cast<unsigned*>(&t);
}
__device__ __forceinline__ void mma16(float* c, unsigned a0, unsigned a1,
                                      unsigned a2, unsigned a3,
                                      unsigned b0, unsigned b1) {
    asm volatile(
        "mma.sync.aligned.m16n8k16.row.col.f32.bf16.bf16.f32 "
        "{%0,%1,%2,%3}, {%4,%5,%6,%7}, {%8,%9}, {%0,%1,%2,%3};\n"
        : "+f"(c[0]), "+f"(c[1]), "+f"(c[2]), "+f"(c[3])
        : "r"(a0), "r"(a1), "r"(a2), "r"(a3), "r"(b0), "r"(b1));
}
__device__ __forceinline__ void ldsm4(unsigned& r0, unsigned& r1,
                                      unsigned& r2, unsigned& r3, unsigned a) {
    asm volatile("ldmatrix.sync.aligned.m8n8.x4.shared.b16 {%0,%1,%2,%3}, [%4];"
                 : "=r"(r0), "=r"(r1), "=r"(r2), "=r"(r3) : "r"(a));
}
__device__ __forceinline__ float w1pad(const float* __restrict__ w1, int kp, int n) {
    const int tap = kp / 24, ch = kp - tap * 24;
    return (ch < 20) ? w1[(tap * 20 + ch) * 32 + n] : 0.f;
}

// 8 warps, 28 (ks,ntp) tasks: conv1 = tasks 0..11, conv2 = tasks 12..27
__global__ void pack_kernel(const float* __restrict__ w1,
                            const float* __restrict__ w2)
{
    const int lane = threadIdx.x & 31, wp = threadIdx.x >> 5;
    const int lr = lane >> 2, lc = lane & 3;
    for (int t = wp; t < 28; t += 8) {
        if (t < 12) {
            const int ks = t >> 1, ntp = t & 1;
            const int kp = 16 * ks + 2 * lc;
            const int n0 = 16 * ntp + lr, n1 = n0 + 8;
            uint4 v;
            v.x = pk(w1pad(w1, kp, n0),     w1pad(w1, kp + 1, n0));
            v.y = pk(w1pad(w1, kp + 8, n0), w1pad(w1, kp + 9, n0));
            v.z = pk(w1pad(w1, kp, n1),     w1pad(w1, kp + 1, n1));
            v.w = pk(w1pad(w1, kp + 8, n1), w1pad(w1, kp + 9, n1));
            d_frag1[ks][ntp][lane] = v;
        } else {
            const int tt = t - 12, ks = tt >> 1, ntp = tt & 1;
            const int k0 = 16 * ks + 2 * lc;
            const int n0 = 16 * ntp + lr, n1 = n0 + 8;
            uint4 v;
            v.x = pk(w2[k0 * 32 + n0],       w2[(k0 + 1) * 32 + n0]);
            v.y = pk(w2[(k0 + 8) * 32 + n0], w2[(k0 + 9) * 32 + n0]);
            v.z = pk(w2[k0 * 32 + n1],       w2[(k0 + 1) * 32 + n1]);
            v.w = pk(w2[(k0 + 8) * 32 + n1], w2[(k0 + 9) * 32 + n1]);
            d_frag2[ks][ntp][lane] = v;
        }
    }
}

// ---------------------------------------------------------------------------
// seq_kernel: warp owns seqs (w, w+8) stacked; 5+5 m16 tiles; warp-local sync
// (byte-identical to the banked 596us version)
// ---------------------------------------------------------------------------
__global__ __launch_bounds__(256, 2) void seq_kernel(
    const float* __restrict__ x,
    const float* __restrict__ b1, const float* __restrict__ b2,
    const float* __restrict__ aw1, const float* __restrict__ ab1,
    const float* __restrict__ aw2, const float* __restrict__ ab2,
    const float* __restrict__ aw3, const float* __restrict__ ab3)
{
    extern __shared__ char sm[];
    __nv_bfloat16* xs  = (__nv_bfloat16*)(sm + XS_OFF);
    __nv_bfloat16* h1s = (__nv_bfloat16*)(sm + H1_OFF);
    float (*es_s)[DIM] = (float(*)[DIM])(sm + ES_OFF);

    const int tid = threadIdx.x;
    const int warp = tid >> 5, lane = tid & 31;
    const int lr = lane >> 2, lc = lane & 3;
    const int rowq = lane & 15;
    const int khalf = (lane >> 4) * 8;

    // ---- stage x: 640 rows -> warp-stacked padded regions ----
    {
        const float4* xg = (const float4*)(x + (long)blockIdx.x * (TSEQ * 40 * 20));
        for (int r = tid; r < TSEQ * 40; r += 256) {
            const int sg = r / 40, t = r - sg * 40;
            const int w = sg & 7, h = sg >> 3;
            const float4 v0 = xg[r * 5], v1 = xg[r * 5 + 1], v2 = xg[r * 5 + 2];
            const float4 v3 = xg[r * 5 + 3], v4 = xg[r * 5 + 4];
            __nv_bfloat16* d = xs + (w * WXROWS + h * 40 + t) * XROW;
            *(uint4*)d = make_uint4(pk(v0.x, v0.y), pk(v0.z, v0.w),
                                    pk(v1.x, v1.y), pk(v1.z, v1.w));
            *(uint4*)(d + 8) = make_uint4(pk(v2.x, v2.y), pk(v2.z, v2.w),
                                          pk(v3.x, v3.y), pk(v3.z, v3.w));
            *(uint2*)(d + 16) = make_uint2(pk(v4.x, v4.y), pk(v4.z, v4.w));
            *(uint2*)(d + 20) = make_uint2(0u, 0u);
        }
    }

    // ---- conv1 fragments + bias ----
    unsigned B1r[6][4][2];
    #pragma unroll
    for (int ks = 0; ks < 6; ++ks) {
        const uint4 v0 = d_frag1[ks][0][lane];
        const uint4 v1 = d_frag1[ks][1][lane];
        B1r[ks][0][0] = v0.x; B1r[ks][0][1] = v0.y;
        B1r[ks][1][0] = v0.z; B1r[ks][1][1] = v0.w;
        B1r[ks][2][0] = v1.x; B1r[ks][2][1] = v1.y;
        B1r[ks][3][0] = v1.z; B1r[ks][3][1] = v1.w;
    }
    float bias1[4][2];
    #pragma unroll
    for (int nt = 0; nt < 4; ++nt) {
        bias1[nt][0] = __ldg(&b1[nt * 8 + 2 * lc]);
        bias1[nt][1] = __ldg(&b1[nt * 8 + 2 * lc + 1]);
    }
    __syncthreads();

    const unsigned xw_s = (unsigned)__cvta_generic_to_shared(xs + warp * WXROWS * XROW);
    const unsigned hw_s = (unsigned)__cvta_generic_to_shared(h1s + warp * WHROWS * H1ROW);
    __nv_bfloat16* Hw = h1s + warp * WHROWS * H1ROW;

    // ---- conv1: 5 tiles over 74 stacked rows (boundary 37) ----
    #pragma unroll
    for (int tile = 0; tile < 5; ++tile) {
        int r = tile * 16 + rowq;
        int rc = r > 73 ? 73 : r;
        const int fr = rc + (rc >= 37 ? 3 : 0);
        const unsigned abase = xw_s + (fr * XROW + khalf) * 2;
        float acc[4][4];
        #pragma unroll
        for (int nt = 0; nt < 4; ++nt) {
            acc[nt][0] = bias1[nt][0]; acc[nt][1] = bias1[nt][1];
            acc[nt][2] = bias1[nt][0]; acc[nt][3] = bias1[nt][1];
        }
        #pragma unroll
        for (int ks = 0; ks < 6; ++ks) {
            unsigned a0, a1, a2, a3;
            ldsm4(a0, a1, a2, a3, abase + ks * 32);
            #pragma unroll
            for (int nt = 0; nt < 4; ++nt)
                mma16(acc[nt], a0, a1, a2, a3, B1r[ks][nt][0], B1r[ks][nt][1]);
        }
        const int r0 = tile * 16 + lr;              // <= 71, always valid
        int r1 = r0 + 8; if (r1 > 73) r1 = 73;      // dup stores benign
        #pragma unroll
        for (int nt = 0; nt < 4; ++nt) {
            const int col = nt * 8 + 2 * lc;
            *(unsigned*)(Hw + r0 * H1ROW + col) =
                pk(selu_f(acc[nt][0]), selu_f(acc[nt][1]));
            *(unsigned*)(Hw + r1 * H1ROW + col) =
                pk(selu_f(acc[nt][2]), selu_f(acc[nt][3]));
        }
    }

    // ---- conv2 fragments + bias ----
    unsigned B2r[8][4][2];
    #pragma unroll
    for (int ks = 0; ks < 8; ++ks) {
        const uint4 v0 = d_frag2[ks][0][lane];
        const uint4 v1 = d_frag2[ks][1][lane];
        B2r[ks][0][0] = v0.x; B2r[ks][0][1] = v0.y;
        B2r[ks][1][0] = v0.z; B2r[ks][1][1] = v0.w;
        B2r[ks][2][0] = v1.x; B2r[ks][2][1] = v1.y;
        B2r[ks][3][0] = v1.z; B2r[ks][3][1] = v1.w;
    }
    float bias2[4][2];
    #pragma unroll
    for (int nt = 0; nt < 4; ++nt) {
        bias2[nt][0] = __ldg(&b2[nt * 8 + 2 * lc]);
        bias2[nt][1] = __ldg(&b2[nt * 8 + 2 * lc + 1]);
    }
    __syncwarp();   // h1 for this warp's seqs written only by this warp

    // ---- conv2: 5 tiles over 68 stacked rows (boundary 34) ----
    float vmA[4][2], vmB[4][2];
    #pragma unroll
    for (int nt = 0; nt < 4; ++nt) {
        vmA[nt][0] = -INFINITY; vmA[nt][1] = -INFINITY;
        vmB[nt][0] = -INFINITY; vmB[nt][1] = -INFINITY;
    }

    #pragma unroll
    for (int tile = 0; tile < 5; ++tile) {
        int r = tile * 16 + rowq;
        int rc = r > 67 ? 67 : r;
        const int fr = rc + (rc >= 34 ? 3 : 0);
        const unsigned abase = hw_s + (fr * H1ROW + khalf) * 2;
        float acc[4][4];
        #pragma unroll
        for (int nt = 0; nt < 4; ++nt) {
            acc[nt][0] = bias2[nt][0]; acc[nt][1] = bias2[nt][1];
            acc[nt][2] = bias2[nt][0]; acc[nt][3] = bias2[nt][1];
        }
        #pragma unroll
        for (int ks = 0; ks < 8; ++ks) {
            unsigned a0, a1, a2, a3;
            ldsm4(a0, a1, a2, a3,
                  abase + ((ks >> 1) * H1ROW + (ks & 1) * 16) * 2);
            #pragma unroll
            for (int nt = 0; nt < 4; ++nt)
                mma16(acc[nt], a0, a1, a2, a3, B2r[ks][nt][0], B2r[ks][nt][1]);
        }
        #pragma unroll
        for (int nt = 0; nt < 4; ++nt) {
            if (tile < 2) {                                    // rows 0..31: A
                vmA[nt][0] = fmaxf(vmA[nt][0], fmaxf(acc[nt][0], acc[nt][2]));
                vmA[nt][1] = fmaxf(vmA[nt][1], fmaxf(acc[nt][1], acc[nt][3]));
            } else if (tile == 2) {                            // rows 32+lr / 40+lr
                if (lr < 2) {                                  // rows 32,33: A
                    vmA[nt][0] = fmaxf(vmA[nt][0], acc[nt][0]);
                    vmA[nt][1] = fmaxf(vmA[nt][1], acc[nt][1]);
                } else {                                       // rows 34..39: B
                    vmB[nt][0] = fmaxf(vmB[nt][0], acc[nt][0]);
                    vmB[nt][1] = fmaxf(vmB[nt][1], acc[nt][1]);
                }
                vmB[nt][0] = fmaxf(vmB[nt][0], acc[nt][2]);    // rows 40..47: B
                vmB[nt][1] = fmaxf(vmB[nt][1], acc[nt][3]);
            } else {                                           // rows 48..67+: B
                vmB[nt][0] = fmaxf(vmB[nt][0], fmaxf(acc[nt][0], acc[nt][2]));
                vmB[nt][1] = fmaxf(vmB[nt][1], fmaxf(acc[nt][1], acc[nt][3]));
            }
        }
        if (tile == 2) {   // seq A complete: reduce + store, free vmA
            #pragma unroll
            for (int nt = 0; nt < 4; ++nt)
                #pragma unroll
                for (int j = 0; j < 2; ++j) {
                    float v = vmA[nt][j];
                    v = fmaxf(v, __shfl_xor_sync(0xffffffffu, v, 4));
                    v = fmaxf(v, __shfl_xor_sync(0xffffffffu, v, 8));
                    v = fmaxf(v, __shfl_xor_sync(0xffffffffu, v, 16));
                    vmA[nt][j] = v;
                }
            if (lane < 4)
                #pragma unroll
                for (int nt = 0; nt < 4; ++nt) {
                    es_s[warp][nt * 8 + 2 * lane]     = selu_f(vmA[nt][0]);
                    es_s[warp][nt * 8 + 2 * lane + 1] = selu_f(vmA[nt][1]);
                }
            __syncwarp();
            g_embed[((long)blockIdx.x * TSEQ + warp) * DIM + lane] = es_s[warp][lane];
        }
    }
    // seq B reduce + store
    #pragma unroll
    for (int nt = 0; nt < 4; ++nt)
        #pragma unroll
        for (int j = 0; j < 2; ++j) {
            float v = vmB[nt][j];
            v = fmaxf(v, __shfl_xor_sync(0xffffffffu, v, 4));
            v = fmaxf(v, __shfl_xor_sync(0xffffffffu, v, 8));
            v = fmaxf(v, __shfl_xor_sync(0xffffffffu, v, 16));
            vmB[nt][j] = v;
        }
    if (lane < 4)
        #pragma unroll
        for (int nt = 0; nt < 4; ++nt) {
            es_s[warp + 8][nt * 8 + 2 * lane]     = selu_f(vmB[nt][0]);
            es_s[warp + 8][nt * 8 + 2 * lane + 1] = selu_f(vmB[nt][1]);
        }
    __syncwarp();
    g_embed[((long)blockIdx.x * TSEQ + warp + 8) * DIM + lane] = es_s[warp + 8][lane];

    // ---- attention MLP: warp handles its two seqs (per-iteration __ldg) ----
    #pragma unroll
    for (int h = 0; h < 2; ++h) {
        const int srow = warp + 8 * h;
        const float* e = es_s[srow];
        const int j = lane;
        float a1v = __ldg(&ab1[j]);
        #pragma unroll 8
        for (int i = 0; i < DIM; ++i)
            a1v = fmaf(e[i], __ldg(&aw1[i * DIM + j]), a1v);
        a1v = selu_f(a1v);
        float a2v = __ldg(&ab2[j]);
        #pragma unroll 8
        for (int i = 0; i < DIM; ++i)
            a2v = fmaf(__shfl_sync(0xffffffffu, a1v, i), __ldg(&aw2[i * DIM + j]), a2v);
        a2v = selu_f(a2v);
        float sc = a2v * __ldg(&aw3[j]);
        #pragma unroll
        for (int o = 16; o > 0; o >>= 1) sc += __shfl_xor_sync(0xffffffffu, sc, o);
        if (j == 0)
            g_scores[(long)blockIdx.x * TSEQ + srow] = sc + __ldg(&ab3[0]);
    }
}

// ---------------------------------------------------------------------------
// bag pipeline: warp-shuffle reductions (2 syncs instead of 10 per pass)
// ---------------------------------------------------------------------------
__global__ __launch_bounds__(1024) void bag_all_kernel(
    const int* __restrict__ nper,
    const float* __restrict__ oaw1, const float* __restrict__ oab1,
    const float* __restrict__ oaw2, const float* __restrict__ oab2,
    const float* __restrict__ obw1, const float* __restrict__ obb1,
    const float* __restrict__ obw2, const float* __restrict__ obb2,
    float* __restrict__ out)
{
    __shared__ float red[32];
    __shared__ float part[32][33];
    __shared__ float pooled[DIM], hA[DIM], hB[DIM];
    __shared__ int s_off, s_cnt;
    __shared__ float s_mx, s_dn;

    const int tid = threadIdx.x, b = blockIdx.x;
    const int wp = tid >> 5, ln = tid & 31;
    if (tid == 0) {
        int off = 0;
        for (int i = 0; i < b; ++i) off += nper[i];
        s_off = off; s_cnt = nper[b];
    }
    __syncthreads();
    const int off = s_off, cnt = s_cnt;

    // segment max (warp shuffle + 32-partial reduce)
    float lm = -INFINITY;
    for (int i = tid; i < cnt; i += 1024) lm = fmaxf(lm, g_scores[off + i]);
    #pragma unroll
    for (int o = 16; o > 0; o >>= 1)
        lm = fmaxf(lm, __shfl_xor_sync(0xffffffffu, lm, o));
    if (ln == 0) red[wp] = lm;
    __syncthreads();
    if (wp == 0) {
        float v = red[ln];
        #pragma unroll
        for (int o = 16; o > 0; o >>= 1)
            v = fmaxf(v, __shfl_xor_sync(0xffffffffu, v, o));
        if (ln == 0) s_mx = v;
    }
    __syncthreads();
    const float mx = s_mx;

    // segment sum of exp
    float ls = 0.f;
    for (int i = tid; i < cnt; i += 1024) ls += __expf(g_scores[off + i] - mx);
    #pragma unroll
    for (int o = 16; o > 0; o >>= 1)
        ls += __shfl_xor_sync(0xffffffffu, ls, o);
    if (ln == 0) red[wp] = ls;
    __syncthreads();
    if (wp == 0) {
        float v = red[ln];
        #pragma unroll
        for (int o = 16; o > 0; o >>= 1)
            v += __shfl_xor_sync(0xffffffffu, v, o);
        if (ln == 0) s_dn = v;
    }
    __syncthreads();
    const float dn = s_dn;

    // weighted pooling: 32 warps, lane = channel
    float acc = 0.f;
    for (int p = wp; p < cnt; p += 32) {
        const float wgt = __expf(g_scores[off + p] - mx);
        acc = fmaf(wgt, g_embed[(long)(off + p) * DIM + ln], acc);
    }
    part[wp][ln] = acc;
    __syncthreads();
    if (tid < DIM) {
        float s = 0.f;
        #pragma unroll
        for (int gg = 0; gg < 32; ++gg) s += part[gg][tid];
        pooled[tid] = s / dn;
    }
    __syncthreads();

    if (tid < DIM) {
        float v = __ldg(&oab1[tid]);
        #pragma unroll 8
        for (int i = 0; i < DIM; ++i) v = fmaf(pooled[i], __ldg(&oaw1[i * DIM + tid]), v);
        hA[tid] = selu_f(v);
    } else if (tid < 2 * DIM) {
        const int k = tid - DIM;
        float v = __ldg(&obb1[k]);
        #pragma unroll 8
        for (int i = 0; i < DIM; ++i) v = fmaf(pooled[i], __ldg(&obw1[i * DIM + k]), v);
        hB[k] = selu_f(v);
    }
    __syncthreads();

    if (tid < 21) {
        float v = __ldg(&oab2[tid]);
        #pragma unroll 8
        for (int i = 0; i < DIM; ++i) v = fmaf(hA[i], __ldg(&oaw2[i * 21 + tid]), v);
        out[b * 21 + tid] = 1.f / (1.f + __expf(-v));
    } else if (tid >= 64 && tid < 104) {
        const int k = tid - 64;
        float v = __ldg(&obb2[k]);
        #pragma unroll 8
        for (int i = 0; i < DIM; ++i) v = fmaf(hB[i], __ldg(&obw2[i * 40 + k]), v);
        out[NBAGS * 21 + b * 40 + k] = 1.f / (1.f + __expf(-v));
    }
}

extern "C" void kernel_launch(void* const* d_in, const int* in_sizes, int n_in,
                              void* d_out, int out_size)
{
    (void)in_sizes; (void)n_in; (void)out_size;
    const float* x    = (const float*)d_in[0];
    const int*   nper = (const int*)  d_in[1];
    const float* w1   = (const float*)d_in[2];
    const float* b1   = (const float*)d_in[3];
    const float* w2   = (const float*)d_in[4];
    const float* b2   = (const float*)d_in[5];
    const float* aw1  = (const float*)d_in[6];
    const float* ab1  = (const float*)d_in[7];
    const float* aw2  = (const float*)d_in[8];
    const float* ab2  = (const float*)d_in[9];
    const float* aw3  = (const float*)d_in[10];
    const float* ab3  = (const float*)d_in[11];
    const float* oaw1 = (const float*)d_in[12];
    const float* oab1 = (const float*)d_in[13];
    const float* oaw2 = (const float*)d_in[14];
    const float* oab2 = (const float*)d_in[15];
    const float* obw1 = (const float*)d_in[16];
    const float* obb1 = (const float*)d_in[17];
    const float* obw2 = (const float*)d_in[18];
    const float* obb2 = (const float*)d_in[19];

    static int init = 0;
    if (!init) {
        cudaFuncSetAttribute(seq_kernel,
                             cudaFuncAttributeMaxDynamicSharedMemorySize,
                             SM_TOTAL);
        init = 1;
    }

    pack_kernel<<<1, 256>>>(w1, w2);
    seq_kernel<<<NBLK, 256, SM_TOTAL>>>(
        x, b1, b2, aw1, ab1, aw2, ab2, aw3, ab3);
    bag_all_kernel<<<NBAGS, 1024>>>(
        nper, oaw1, oab1, oaw2, oab2, obw1, obb1, obw2, obb2, (float*)d_out);
}